// round 3
// baseline (speedup 1.0000x reference)
#include <cuda_runtime.h>
#include <math.h>

#define NN 8192
#define DD 128
#define KNN 10
#define KP1 11
#define ROWS 64          // rows per block in dist kernel
#define CTILE 128        // columns per tile
#define NCHUNK 4         // column chunks (for wave balance)
#define CHUNK 2048       // columns per chunk
#define NTILES 16        // CHUNK / CTILE
#define SA_S 129         // padded smem strides (odd -> conflict-free reads)
#define SB_S 129

// ---------------- device scratch (no allocation allowed) ----------------
__device__ float g_norm[2][NN];                    // squared row norms
__device__ float g_part[2][NN][NCHUNK][KP1];       // per-chunk top-11 (ascending)
__device__ float g_ab[2][NN][KNN];                 // normalized knn dists (a, b)
__device__ float g_bpart[32];                      // sinkhorn block partial sums

// ---------------- kernel 1: squared norms (warp per row) ----------------
__global__ void norms_kernel(const float* __restrict__ x0,
                             const float* __restrict__ x1) {
    const float* x = blockIdx.y ? x1 : x0;
    int row  = blockIdx.x * (blockDim.x >> 5) + (threadIdx.x >> 5);
    int lane = threadIdx.x & 31;
    float4 v = reinterpret_cast<const float4*>(x + (size_t)row * DD)[lane];
    float s = v.x * v.x + v.y * v.y + v.z * v.z + v.w * v.w;
#pragma unroll
    for (int o = 16; o; o >>= 1) s += __shfl_xor_sync(0xffffffffu, s, o);
    if (lane == 0) g_norm[blockIdx.y][row] = s;
}

// Insert v into descending-sorted 11-list (L[0] = largest kept = threshold)
__device__ __forceinline__ void insert11(float (&L)[KP1], float v) {
    if (v < L[0]) {
        L[0] = v;
#pragma unroll
        for (int i = 0; i < KP1 - 1; i++) {
            float lo = L[i], hi = L[i + 1];
            if (lo < hi) { L[i] = hi; L[i + 1] = lo; }
        }
    }
}

// -------- kernel 2: fused distance GEMM + per-row top-11 (per chunk) ----
// grid: (128 row-stripes, 4 col-chunks, 2 matrices), 256 threads.
// Thread (ty=tid/8, tx=tid&7): rows {2ty, 2ty+1}, cols {tx + 8c : c=0..15}.
__global__ void __launch_bounds__(256, 1)
dist_topk_kernel(const float* __restrict__ x0, const float* __restrict__ x1) {
    extern __shared__ float sm[];
    float* sA  = sm;                       // 64 x 129
    float* sB  = sA + ROWS * SA_S;         // 128 x 129
    float* sNA = sB + CTILE * SB_S;        // 64
    float* sNB = sNA + ROWS;               // 128
    float* sM  = sNB + CTILE;              // 64 * 8 * 11 merge area

    const int mat = blockIdx.z;
    const float* X = mat ? x1 : x0;
    const int r0 = blockIdx.x * ROWS;
    const int c0 = blockIdx.y * CHUNK;

    const int tid = threadIdx.x;
    const int tx = tid & 7;
    const int ty = tid >> 3;

    // load A stripe [64 x 128] (coalesced float4 loads, scalar smem stores)
    for (int s = tid; s < ROWS * (DD / 4); s += 256) {
        int r = s >> 5, c4 = s & 31;
        float4 v = reinterpret_cast<const float4*>(X + (size_t)(r0 + r) * DD)[c4];
        float* p = sA + r * SA_S + c4 * 4;
        p[0] = v.x; p[1] = v.y; p[2] = v.z; p[3] = v.w;
    }
    if (tid < ROWS) sNA[tid] = g_norm[mat][r0 + tid];
    __syncthreads();

    const float sqa0 = sNA[ty * 2];
    const float sqa1 = sNA[ty * 2 + 1];

    float best[2][KP1];
#pragma unroll
    for (int r = 0; r < 2; r++)
#pragma unroll
        for (int i = 0; i < KP1; i++) best[r][i] = 1e30f;

    const float* pa = sA + (ty * 2) * SA_S;
    const float* pb = sB + tx * SB_S;

    for (int t = 0; t < NTILES; t++) {
        const int j0 = c0 + t * CTILE;
        // load B tile [128 x 128]
        for (int s = tid; s < CTILE * (DD / 4); s += 256) {
            int j = s >> 5, c4 = s & 31;
            float4 v = reinterpret_cast<const float4*>(X + (size_t)(j0 + j) * DD)[c4];
            float* p = sB + j * SB_S + c4 * 4;
            p[0] = v.x; p[1] = v.y; p[2] = v.z; p[3] = v.w;
        }
        if (tid < CTILE) sNB[tid] = g_norm[mat][j0 + tid];
        __syncthreads();

        float acc0[16], acc1[16];
#pragma unroll
        for (int c = 0; c < 16; c++) { acc0[c] = 0.f; acc1[c] = 0.f; }

#pragma unroll 2
        for (int kk = 0; kk < DD; kk++) {
            float a0 = pa[kk];
            float a1 = pa[SA_S + kk];
#pragma unroll
            for (int c = 0; c < 16; c++) {
                float b = pb[c * 8 * SB_S + kk];   // constant smem imm offsets
                acc0[c] = fmaf(a0, b, acc0[c]);
                acc1[c] = fmaf(a1, b, acc1[c]);
            }
        }

        // distances + top-11 insertion
#pragma unroll
        for (int c = 0; c < 16; c++) {
            float sqb = sNB[tx + 8 * c];
            float d0 = sqrtf(fmaxf(sqa0 + sqb - 2.0f * acc0[c], 1e-12f));
            float d1 = sqrtf(fmaxf(sqa1 + sqb - 2.0f * acc1[c], 1e-12f));
            insert11(best[0], d0);
            insert11(best[1], d1);
        }
        __syncthreads();   // protect sB/sNB before next tile's stores
    }

    // dump per-thread lists (ascending) and merge 8 lists per row
#pragma unroll
    for (int r = 0; r < 2; r++) {
        float* p = sM + ((ty * 2 + r) * 8 + tx) * KP1;
#pragma unroll
        for (int i = 0; i < KP1; i++) p[i] = best[r][KP1 - 1 - i];
    }
    __syncthreads();

    if (tid < ROWS) {
        float* p = sM + tid * 8 * KP1;          // 88 candidates
        float* out = g_part[mat][r0 + tid][blockIdx.y];
        for (int s = 0; s < KP1; s++) {
            float mn = 1e30f; int am = 0;
            for (int q = 0; q < 8 * KP1; q++) {
                float v = p[q];
                if (v < mn) { mn = v; am = q; }
            }
            p[am] = 1e30f;
            out[s] = mn;                         // ascending
        }
    }
}

// -------- kernel 3: merge 4 chunk-lists, drop self, normalize -----------
__global__ void merge_norm_kernel() {
    int gid = blockIdx.x * blockDim.x + threadIdx.x;   // 0..16383
    if (gid >= 2 * NN) return;
    int mat = gid >> 13;
    int row = gid & (NN - 1);

    float vals[NCHUNK * KP1];
#pragma unroll
    for (int c = 0; c < NCHUNK; c++)
#pragma unroll
        for (int i = 0; i < KP1; i++)
            vals[c * KP1 + i] = g_part[mat][row][c][i];

    float sel[KP1];
    for (int s = 0; s < KP1; s++) {
        float mn = 1e30f; int am = 0;
        for (int q = 0; q < NCHUNK * KP1; q++)
            if (vals[q] < mn) { mn = vals[q]; am = q; }
        vals[am] = 1e30f;
        sel[s] = mn;
    }
    // sel[0] is the ~0 self-distance -> dropped (matches sort()[:,1:k+1])
    float sum = 0.f;
#pragma unroll
    for (int i = 1; i < KP1; i++) sum += sel[i];
    float inv = 1.0f / (sum + 1e-10f);
#pragma unroll
    for (int i = 1; i < KP1; i++) g_ab[mat][row][i - 1] = sel[i] * inv;
}

// -------- kernel 4: per-sample Sinkhorn, all in registers ---------------
__global__ void __launch_bounds__(256, 1) sinkhorn_kernel() {
    const int row = blockIdx.x * 256 + threadIdx.x;    // 8192 threads exactly

    float a[KNN], b[KNN], u[KNN], v[KNN], E[KNN], KM[KNN];
#pragma unroll
    for (int i = 0; i < KNN; i++) {
        a[i] = g_ab[0][row][i];
        b[i] = g_ab[1][row][i];
        u[i] = 1.0f;
    }
#pragma unroll
    for (int d = 0; d < KNN; d++) {
        float m = (float)d / 10.0f;            // M_ij = |i-j|/k
        E[d]  = expf(-m / 0.1f);               // K = exp(-M/reg)
        KM[d] = E[d] * m;                      // K ∘ M
    }

    const float EPSf = 1e-10f;
#pragma unroll 1
    for (int it = 0; it < 50; it++) {
#pragma unroll
        for (int i = 0; i < KNN; i++) {
            float s = 0.f;
#pragma unroll
            for (int j = 0; j < KNN; j++) s = fmaf(E[i > j ? i - j : j - i], u[j], s);
            v[i] = __fdividef(b[i], s + EPSf);
        }
#pragma unroll
        for (int i = 0; i < KNN; i++) {
            float s = 0.f;
#pragma unroll
            for (int j = 0; j < KNN; j++) s = fmaf(E[i > j ? i - j : j - i], v[j], s);
            u[i] = __fdividef(a[i], s + EPSf);
        }
    }
    // final v = b / (u @ K + eps)
#pragma unroll
    for (int i = 0; i < KNN; i++) {
        float s = 0.f;
#pragma unroll
        for (int j = 0; j < KNN; j++) s = fmaf(E[i > j ? i - j : j - i], u[j], s);
        v[i] = __fdividef(b[i], s + EPSf);
    }
    // cost = sum_ij u_i (K∘M)_ij v_j   (diagonal terms are 0)
    float cost = 0.f;
#pragma unroll
    for (int i = 0; i < KNN; i++) {
        float s = 0.f;
#pragma unroll
        for (int j = 0; j < KNN; j++) {
            int d = i > j ? i - j : j - i;
            if (d) s = fmaf(KM[d], v[j], s);
        }
        cost = fmaf(u[i], s, cost);
    }

    // deterministic block reduction
#pragma unroll
    for (int o = 16; o; o >>= 1) cost += __shfl_xor_sync(0xffffffffu, cost, o);
    __shared__ float ws[8];
    if ((threadIdx.x & 31) == 0) ws[threadIdx.x >> 5] = cost;
    __syncthreads();
    if (threadIdx.x < 8) {
        float c = ws[threadIdx.x];
#pragma unroll
        for (int o = 4; o; o >>= 1) c += __shfl_xor_sync(0x000000ffu, c, o);
        if (threadIdx.x == 0) g_bpart[blockIdx.x] = c;
    }
}

// -------- kernel 5: final deterministic reduction -> mean ---------------
__global__ void finalize_kernel(float* __restrict__ out) {
    float c = g_bpart[threadIdx.x];   // 32 partials
#pragma unroll
    for (int o = 16; o; o >>= 1) c += __shfl_xor_sync(0xffffffffu, c, o);
    if (threadIdx.x == 0) out[0] = c * (1.0f / 8192.0f);
}

// ------------------------------ launcher --------------------------------
extern "C" void kernel_launch(void* const* d_in, const int* in_sizes, int n_in,
                              void* d_out, int out_size) {
    const float* x0 = (const float*)d_in[0];   // embeddings [8192,128]
    const float* x1 = (const float*)d_in[1];   // reference_embeddings
    float* out = (float*)d_out;

    norms_kernel<<<dim3(1024, 2), 256>>>(x0, x1);

    const size_t smem = (size_t)(ROWS * SA_S + CTILE * SB_S + ROWS + CTILE +
                                 ROWS * 8 * KP1) * sizeof(float);   // ~120 KB
    cudaFuncSetAttribute(dist_topk_kernel,
                         cudaFuncAttributeMaxDynamicSharedMemorySize, (int)smem);
    dist_topk_kernel<<<dim3(NN / ROWS, NCHUNK, 2), 256, smem>>>(x0, x1);

    merge_norm_kernel<<<(2 * NN) / 256, 256>>>();
    sinkhorn_kernel<<<NN / 256, 256>>>();
    finalize_kernel<<<1, 32>>>(out);
}

// round 5
// speedup vs baseline: 4.3203x; 4.3203x over previous
#include <cuda_runtime.h>
#include <math.h>
#include <stdint.h>

#define NN 8192
#define DD 128
#define KNN 10
#define KP1 11
#define STRIDE 132                      // padded floats per smem row
#define TILE_F (128 * STRIDE)           // floats per [128x128] tile buffer

// ---------------- device scratch (no allocation allowed) ----------------
__device__ __align__(16) float g_norm[2][NN];      // squared row norms
__device__ float g_ab[2][NN][KNN];                 // normalized knn dists (a, b)
__device__ float g_bpart[128];                     // sinkhorn block partials

// ======================= small PTX helpers ===============================
__device__ __forceinline__ uint32_t smem_u32(const void* p) {
    uint32_t a;
    asm("{ .reg .u64 t; cvta.to.shared.u64 t, %1; cvt.u32.u64 %0, t; }"
        : "=r"(a) : "l"(p));
    return a;
}

__device__ __forceinline__ void mma_tf32(float* c, float a0, float a1,
                                         float a2, float a3,
                                         float b0, float b1) {
    asm volatile(
        "mma.sync.aligned.m16n8k8.row.col.f32.tf32.tf32.f32 "
        "{%0,%1,%2,%3}, {%4,%5,%6,%7}, {%8,%9}, {%0,%1,%2,%3};"
        : "+f"(c[0]), "+f"(c[1]), "+f"(c[2]), "+f"(c[3])
        : "r"(__float_as_uint(a0)), "r"(__float_as_uint(a1)),
          "r"(__float_as_uint(a2)), "r"(__float_as_uint(a3)),
          "r"(__float_as_uint(b0)), "r"(__float_as_uint(b1)));
}

#define CP_ASYNC16(dst, src) \
    asm volatile("cp.async.cg.shared.global [%0], [%1], 16;" \
                 :: "r"(dst), "l"(src))
#define CP_COMMIT() asm volatile("cp.async.commit_group;" ::: "memory")
#define CP_WAIT0()  asm volatile("cp.async.wait_group 0;" ::: "memory")

// ---------------- kernel 1: squared norms (warp per row) ----------------
__global__ void norms_kernel(const float* __restrict__ x0,
                             const float* __restrict__ x1) {
    const float* x = blockIdx.y ? x1 : x0;
    int row  = blockIdx.x * (blockDim.x >> 5) + (threadIdx.x >> 5);
    int lane = threadIdx.x & 31;
    float4 v = reinterpret_cast<const float4*>(x + (size_t)row * DD)[lane];
    float s = v.x * v.x + v.y * v.y + v.z * v.z + v.w * v.w;
#pragma unroll
    for (int o = 16; o; o >>= 1) s += __shfl_xor_sync(0xffffffffu, s, o);
    if (lane == 0) g_norm[blockIdx.y][row] = s;
}

// Insert v into descending-sorted 11-list (L[0] = largest kept)
__device__ __forceinline__ void insert11(float (&L)[KP1], float v) {
    if (v < L[0]) {
        L[0] = v;
#pragma unroll
        for (int i = 0; i < KP1 - 1; i++) {
            float lo = fminf(L[i], L[i + 1]);
            float hi = fmaxf(L[i], L[i + 1]);
            L[i] = hi; L[i + 1] = lo;
        }
    }
}

// async-copy one [128x128] B tile + its 128 norms into smem
__device__ __forceinline__ void cp_tile(float* dstB, float* dstN,
                                        const float* __restrict__ X,
                                        int t, int tid, int mat) {
    const float* src = X + (size_t)t * 128 * DD;
#pragma unroll
    for (int i = 0; i < 16; i++) {
        int c = tid + i * 256;                       // float4 chunk id
        int r = c >> 5, q = c & 31;
        uint32_t d = smem_u32(dstB + r * STRIDE + q * 4);
        CP_ASYNC16(d, src + (size_t)r * DD + q * 4);
    }
    if (tid < 32) {
        uint32_t d = smem_u32(dstN + tid * 4);
        CP_ASYNC16(d, &g_norm[mat][t * 128 + tid * 4]);
    }
}

// ------ kernel 2: tf32 mma.sync Gram + per-row top-11 --------------------
// block = 256 thr (8 warps); warp w owns rows r0 + w*16 .. +15.
__global__ void __launch_bounds__(256, 1)
dist_knn_kernel(const float* __restrict__ x0, const float* __restrict__ x1) {
    extern __shared__ float sm[];
    float* sA   = sm;                        // [128][STRIDE]
    float* sB   = sm + TILE_F;               // 2 x [128][STRIDE]
    float* snrm = sm + 3 * TILE_F;           // 2 x [128]
    float* smrg = sB;                        // merge area aliases sB0 at end

    const int mat = blockIdx.y;
    const float* X = mat ? x1 : x0;
    const int r0 = blockIdx.x * 128;
    const int tid  = threadIdx.x;
    const int w    = tid >> 5;
    const int lane = tid & 31;
    const int g    = lane >> 2;              // 0..7
    const int tg   = lane & 3;               // 0..3

    // load A stripe [128 x 128] into padded smem (coalesced)
#pragma unroll
    for (int i = 0; i < 16; i++) {
        int c = tid + i * 256;
        int r = c >> 5, q = c & 31;
        float4 v = reinterpret_cast<const float4*>(X + (size_t)(r0 + r) * DD)[q];
        float* p = sA + r * STRIDE + q * 4;
        p[0] = v.x; p[1] = v.y; p[2] = v.z; p[3] = v.w;
    }
    // prologue: async-load B tile 0
    cp_tile(sB, snrm, X, 0, tid, mat);
    CP_COMMIT();
    __syncthreads();                         // sA visible

    float best0[KP1], best1[KP1];
#pragma unroll
    for (int i = 0; i < KP1; i++) { best0[i] = 1e30f; best1[i] = 1e30f; }

    const float* pa = sA + (w * 16) * STRIDE;

    for (int t = 0; t < 64; t++) {
        const int p = t & 1;
        CP_WAIT0();
        __syncthreads();   // B(t)+norms(t) visible; all warps done with buf p

        if (t + 1 < 64) {
            cp_tile(sB + (1 - p) * TILE_F, snrm + (1 - p) * 128,
                    X, t + 1, tid, mat);
            CP_COMMIT();
        }

        const float* pb = sB + p * TILE_F;
        float acc[16][4];
#pragma unroll
        for (int n = 0; n < 16; n++) {
            acc[n][0] = 0.f; acc[n][1] = 0.f; acc[n][2] = 0.f; acc[n][3] = 0.f;
        }

#pragma unroll 4
        for (int s = 0; s < 16; s++) {
            const float* par = pa + s * 8 + tg;
            float a0 = par[g * STRIDE];
            float a1 = par[(g + 8) * STRIDE];
            float a2 = par[g * STRIDE + 4];
            float a3 = par[(g + 8) * STRIDE + 4];
            const float* pbr = pb + g * STRIDE + s * 8 + tg;
#pragma unroll
            for (int n = 0; n < 16; n++) {
                float b0 = pbr[n * 8 * STRIDE];
                float b1 = pbr[n * 8 * STRIDE + 4];
                mma_tf32(acc[n], a0, a1, a2, a3, b0, b1);
            }
        }

        // epilogue: key = sqb - 2*dot (same order as d^2)
        const float* nb = snrm + p * 128;
#pragma unroll
        for (int n = 0; n < 16; n++) {
            float2 nv = *reinterpret_cast<const float2*>(nb + n * 8 + 2 * tg);
            insert11(best0, fmaf(-2.f, acc[n][0], nv.x));
            insert11(best0, fmaf(-2.f, acc[n][1], nv.y));
            insert11(best1, fmaf(-2.f, acc[n][2], nv.x));
            insert11(best1, fmaf(-2.f, acc[n][3], nv.y));
        }
        // no trailing sync needed: next iter's top sync orders buffer reuse
    }

    __syncthreads();                         // all compute done; reuse sB0
    // dump per-thread lists (ascending) : rows w*16+g and w*16+g+8, slot tg
    {
        float* L0 = smrg + ((size_t)((w * 16 + g) * 4 + tg)) * KP1;
        float* L1 = smrg + ((size_t)((w * 16 + g + 8) * 4 + tg)) * KP1;
#pragma unroll
        for (int i = 0; i < KP1; i++) {
            L0[i] = best0[KP1 - 1 - i];
            L1[i] = best1[KP1 - 1 - i];
        }
    }
    __syncthreads();

    if (tid < 128) {
        float* cand = smrg + (size_t)tid * 4 * KP1;   // 44 candidates
        float sel[KP1];
        for (int s = 0; s < KP1; s++) {
            float mn = 1e30f; int am = 0;
            for (int q = 0; q < 4 * KP1; q++) {
                float v = cand[q];
                if (v < mn) { mn = v; am = q; }
            }
            cand[am] = 1e30f;
            sel[s] = mn;                               // ascending keys
        }
        const int row = r0 + tid;
        const float sqa = g_norm[mat][row];
        float d[KP1];
#pragma unroll
        for (int i = 0; i < KP1; i++)
            d[i] = sqrtf(fmaxf(sel[i] + sqa, 1e-12f)); // d[0] = self ~ 0
        float sum = 0.f;
#pragma unroll
        for (int i = 1; i < KP1; i++) sum += d[i];
        float inv = 1.0f / (sum + 1e-10f);
#pragma unroll
        for (int j = 0; j < KNN; j++)
            g_ab[mat][row][j] = d[j + 1] * inv;        // ascending knn
    }
}

// -------- kernel 3: per-sample Sinkhorn (128 blocks x 64 thr) ------------
__global__ void __launch_bounds__(64, 1) sinkhorn_kernel() {
    const int row = blockIdx.x * 64 + threadIdx.x;     // 8192 threads

    float a[KNN], b[KNN], u[KNN], v[KNN], E[KNN], KM[KNN];
#pragma unroll
    for (int i = 0; i < KNN; i++) {
        a[i] = g_ab[0][row][i];
        b[i] = g_ab[1][row][i];
        u[i] = 1.0f;
    }
#pragma unroll
    for (int dd = 0; dd < KNN; dd++) {
        float m = (float)dd / 10.0f;
        E[dd]  = expf(-m / 0.1f);
        KM[dd] = E[dd] * m;
    }

    const float EPSf = 1e-10f;
#pragma unroll 1
    for (int it = 0; it < 50; it++) {
#pragma unroll
        for (int i = 0; i < KNN; i++) {
            float s = 0.f;
#pragma unroll
            for (int j = 0; j < KNN; j++)
                s = fmaf(E[i > j ? i - j : j - i], u[j], s);
            v[i] = __fdividef(b[i], s + EPSf);
        }
#pragma unroll
        for (int i = 0; i < KNN; i++) {
            float s = 0.f;
#pragma unroll
            for (int j = 0; j < KNN; j++)
                s = fmaf(E[i > j ? i - j : j - i], v[j], s);
            u[i] = __fdividef(a[i], s + EPSf);
        }
    }
#pragma unroll
    for (int i = 0; i < KNN; i++) {
        float s = 0.f;
#pragma unroll
        for (int j = 0; j < KNN; j++)
            s = fmaf(E[i > j ? i - j : j - i], u[j], s);
        v[i] = __fdividef(b[i], s + EPSf);
    }
    float cost = 0.f;
#pragma unroll
    for (int i = 0; i < KNN; i++) {
        float s = 0.f;
#pragma unroll
        for (int j = 0; j < KNN; j++) {
            int dd = i > j ? i - j : j - i;
            if (dd) s = fmaf(KM[dd], v[j], s);
        }
        cost = fmaf(u[i], s, cost);
    }

#pragma unroll
    for (int o = 16; o; o >>= 1) cost += __shfl_xor_sync(0xffffffffu, cost, o);
    __shared__ float ws[2];
    if ((threadIdx.x & 31) == 0) ws[threadIdx.x >> 5] = cost;
    __syncthreads();
    if (threadIdx.x == 0) g_bpart[blockIdx.x] = ws[0] + ws[1];
}

// -------- kernel 4: final deterministic reduction -> mean ----------------
__global__ void finalize_kernel(float* __restrict__ out) {
    float c = 0.f;
#pragma unroll
    for (int i = 0; i < 4; i++) c += g_bpart[threadIdx.x * 4 + i];
#pragma unroll
    for (int o = 16; o; o >>= 1) c += __shfl_xor_sync(0xffffffffu, c, o);
    if (threadIdx.x == 0) out[0] = c * (1.0f / 8192.0f);
}

// ------------------------------ launcher ---------------------------------
extern "C" void kernel_launch(void* const* d_in, const int* in_sizes, int n_in,
                              void* d_out, int out_size) {
    const float* x0 = (const float*)d_in[0];   // embeddings [8192,128]
    const float* x1 = (const float*)d_in[1];   // reference_embeddings
    float* out = (float*)d_out;

    norms_kernel<<<dim3(1024, 2), 256>>>(x0, x1);

    const int smem = (3 * TILE_F + 256) * (int)sizeof(float);   // ~204 KB
    cudaFuncSetAttribute(dist_knn_kernel,
                         cudaFuncAttributeMaxDynamicSharedMemorySize, smem);
    dist_knn_kernel<<<dim3(64, 2), 256, smem>>>(x0, x1);

    sinkhorn_kernel<<<128, 64>>>();
    finalize_kernel<<<1, 32>>>(out);
}